// round 1
// baseline (speedup 1.0000x reference)
#include <cuda_runtime.h>
#include <cuda_bf16.h>
#include <math.h>

// Problem dims (fixed by the dataset)
#define T 4096
#define E 512

// -------------------- scratch (allocation-free: __device__ globals) ---------
__device__ float g_h1[(size_t)T * E];
__device__ float g_h2[(size_t)T * E];
__device__ float g_dot[(size_t)T * T];
__device__ float g_lg[(size_t)T * T];
__device__ float g_cmax[T];
__device__ float g_csum[T];

// -------------------- fp32 NT GEMM: C[m,n] = sum_k A[m,k]*B[n,k] (+bias[n]) -
// A: M x K row-major, B: N x K row-major, C: M x N row-major.
// BM=BN=128, BK=16, 256 threads, 8x8 per-thread micro-tile.
#define BM 128
#define BN 128
#define BK 16
#define ASTRIDE (BM + 4)   // float4-aligned, 2-way STS conflict max

__global__ __launch_bounds__(256) void gemm_nt(const float* __restrict__ A,
                                               const float* __restrict__ B,
                                               const float* __restrict__ bias,
                                               float* __restrict__ C,
                                               int M, int N, int K) {
    __shared__ float As[BK][ASTRIDE];
    __shared__ float Bs[BK][ASTRIDE];

    const int tid = threadIdx.x;
    const int m0 = blockIdx.y * BM;
    const int n0 = blockIdx.x * BN;
    const int tx = tid & 15;       // 0..15 -> n micro
    const int ty = tid >> 4;       // 0..15 -> m micro

    float acc[8][8];
#pragma unroll
    for (int i = 0; i < 8; i++)
#pragma unroll
        for (int j = 0; j < 8; j++) acc[i][j] = 0.f;

    for (int k0 = 0; k0 < K; k0 += BK) {
        // ---- load tiles: 128 rows x 16 k = 512 float4s, 2 per thread -------
#pragma unroll
        for (int it = 0; it < 2; it++) {
            int idx = tid + it * 256;          // 0..511
            int row = idx >> 2;                // 0..127
            int kk = (idx & 3) << 2;           // 0,4,8,12
            float4 av = *(const float4*)(A + (size_t)(m0 + row) * K + k0 + kk);
            As[kk + 0][row] = av.x;
            As[kk + 1][row] = av.y;
            As[kk + 2][row] = av.z;
            As[kk + 3][row] = av.w;
            float4 bv = *(const float4*)(B + (size_t)(n0 + row) * K + k0 + kk);
            Bs[kk + 0][row] = bv.x;
            Bs[kk + 1][row] = bv.y;
            Bs[kk + 2][row] = bv.z;
            Bs[kk + 3][row] = bv.w;
        }
        __syncthreads();

        // ---- compute -------------------------------------------------------
#pragma unroll
        for (int k = 0; k < BK; k++) {
            float ra[8], rb[8];
#pragma unroll
            for (int i = 0; i < 8; i++) ra[i] = As[k][ty * 8 + i];
#pragma unroll
            for (int j = 0; j < 8; j++) rb[j] = Bs[k][tx * 8 + j];
#pragma unroll
            for (int i = 0; i < 8; i++)
#pragma unroll
                for (int j = 0; j < 8; j++) acc[i][j] += ra[i] * rb[j];
        }
        __syncthreads();
    }

    // ---- epilogue ----------------------------------------------------------
    float bv[8];
#pragma unroll
    for (int j = 0; j < 8; j++) bv[j] = bias ? bias[n0 + tx * 8 + j] : 0.f;

#pragma unroll
    for (int i = 0; i < 8; i++) {
        int m = m0 + ty * 8 + i;
        float4 lo, hi;
        lo.x = acc[i][0] + bv[0]; lo.y = acc[i][1] + bv[1];
        lo.z = acc[i][2] + bv[2]; lo.w = acc[i][3] + bv[3];
        hi.x = acc[i][4] + bv[4]; hi.y = acc[i][5] + bv[5];
        hi.z = acc[i][6] + bv[6]; hi.w = acc[i][7] + bv[7];
        float* cp = C + (size_t)m * N + n0 + tx * 8;
        *(float4*)(cp) = lo;
        *(float4*)(cp + 4) = hi;
    }
}

// -------------------- banded window sum + global add ------------------------
// lg[i,j] = sum_{k=i-63}^{i+63, clamped} dot[k,j] + gatt[i,j]
// Block: 128 output rows x 32 cols. smem holds 254 rows (63-row halo each side).
#define WR 128
#define WC 32
#define HALO 63

__global__ __launch_bounds__(256) void window_kernel(const float* __restrict__ dot,
                                                     const float* __restrict__ gatt,
                                                     float* __restrict__ lg) {
    __shared__ float s[WR + 2 * HALO][WC];   // 254 x 32 floats = 32512 B

    const int r0 = blockIdx.y * WR;
    const int c0 = blockIdx.x * WC;
    const int tid = threadIdx.x;
    const int col = tid & 31;

    // load (zero-padded outside [0,T))
    for (int rr = tid >> 5; rr < WR + 2 * HALO; rr += 8) {
        int gr = r0 - HALO + rr;
        float v = 0.f;
        if (gr >= 0 && gr < T) v = dot[(size_t)gr * T + c0 + col];
        s[rr][col] = v;
    }
    __syncthreads();

    const int strip = tid >> 5;    // 0..7
    const int i0 = strip * 16;     // local output row base

    // initial full window: smem rows [i0, i0+126] (4 partial accumulators)
    float w0 = 0.f, w1 = 0.f, w2 = 0.f, w3 = 0.f;
#pragma unroll 8
    for (int t = 0; t < 124; t += 4) {
        w0 += s[i0 + t + 0][col];
        w1 += s[i0 + t + 1][col];
        w2 += s[i0 + t + 2][col];
        w3 += s[i0 + t + 3][col];
    }
    w0 += s[i0 + 124][col];
    w1 += s[i0 + 125][col];
    w2 += s[i0 + 126][col];
    float w = (w0 + w1) + (w2 + w3);

#pragma unroll
    for (int t = 0; t < 16; t++) {
        int gi = r0 + i0 + t;
        float val = w + gatt[(size_t)gi * T + c0 + col];
        lg[(size_t)gi * T + c0 + col] = val;
        if (t < 15) w += s[i0 + t + 127][col] - s[i0 + t][col];
    }
}

// -------------------- per-column max + sum(exp) -----------------------------
__global__ __launch_bounds__(256) void colreduce(const float* __restrict__ lg,
                                                 float* __restrict__ cmax,
                                                 float* __restrict__ csum) {
    const int c0 = blockIdx.x * 32;
    const int col = threadIdx.x & 31;
    const int seg = threadIdx.x >> 5;       // 0..7 -> 512-row segment
    const int rbeg = seg * 512;

    __shared__ float sm[8][32];
    __shared__ float ss[8][32];

    float m0 = -1e30f, m1 = -1e30f, m2 = -1e30f, m3 = -1e30f;
    for (int r = rbeg; r < rbeg + 512; r += 4) {
        m0 = fmaxf(m0, lg[(size_t)(r + 0) * T + c0 + col]);
        m1 = fmaxf(m1, lg[(size_t)(r + 1) * T + c0 + col]);
        m2 = fmaxf(m2, lg[(size_t)(r + 2) * T + c0 + col]);
        m3 = fmaxf(m3, lg[(size_t)(r + 3) * T + c0 + col]);
    }
    sm[seg][col] = fmaxf(fmaxf(m0, m1), fmaxf(m2, m3));
    __syncthreads();
    if (seg == 0) {
        float mm = sm[0][col];
#pragma unroll
        for (int i = 1; i < 8; i++) mm = fmaxf(mm, sm[i][col]);
        sm[0][col] = mm;
    }
    __syncthreads();
    const float M = sm[0][col];

    float s0 = 0.f, s1 = 0.f, s2 = 0.f, s3 = 0.f;
    for (int r = rbeg; r < rbeg + 512; r += 4) {
        s0 += expf(lg[(size_t)(r + 0) * T + c0 + col] - M);
        s1 += expf(lg[(size_t)(r + 1) * T + c0 + col] - M);
        s2 += expf(lg[(size_t)(r + 2) * T + c0 + col] - M);
        s3 += expf(lg[(size_t)(r + 3) * T + c0 + col] - M);
    }
    ss[seg][col] = (s0 + s1) + (s2 + s3);
    __syncthreads();
    if (seg == 0) {
        float tt = 0.f;
#pragma unroll
        for (int i = 0; i < 8; i++) tt += ss[i][col];
        cmax[c0 + col] = M;
        csum[c0 + col] = tt;
    }
}

// -------------------- finalize: out = exp(lg - max_col) / sum_col -----------
__global__ __launch_bounds__(256) void finalize_kernel(const float* __restrict__ lg,
                                                       const float* __restrict__ cmax,
                                                       const float* __restrict__ csum,
                                                       float* __restrict__ out) {
    size_t i = (size_t)blockIdx.x * blockDim.x + threadIdx.x;
    size_t base = i * 4;
    int c = (int)(base & (T - 1));
    float4 v = *(const float4*)(lg + base);
    float4 M = *(const float4*)(cmax + c);
    float4 S = *(const float4*)(csum + c);
    float4 o;
    o.x = expf(v.x - M.x) / S.x;
    o.y = expf(v.y - M.y) / S.y;
    o.z = expf(v.z - M.z) / S.z;
    o.w = expf(v.w - M.w) / S.w;
    *(float4*)(out + base) = o;
}

// -------------------- launch ------------------------------------------------
extern "C" void kernel_launch(void* const* d_in, const int* in_sizes, int n_in,
                              void* d_out, int out_size) {
    const float* x1 = (const float*)d_in[0];   // (T, T)
    const float* x2 = (const float*)d_in[1];   // (T, T)
    const float* W1 = (const float*)d_in[2];   // (E, T)
    const float* b1 = (const float*)d_in[3];   // (E,)
    const float* W2 = (const float*)d_in[4];   // (E, T)
    const float* b2 = (const float*)d_in[5];   // (E,)
    const float* ga = (const float*)d_in[6];   // (T, T)
    float* out = (float*)d_out;

    float *h1, *h2, *dot, *lg, *cmax, *csum;
    cudaGetSymbolAddress((void**)&h1, g_h1);
    cudaGetSymbolAddress((void**)&h2, g_h2);
    cudaGetSymbolAddress((void**)&dot, g_dot);
    cudaGetSymbolAddress((void**)&lg, g_lg);
    cudaGetSymbolAddress((void**)&cmax, g_cmax);
    cudaGetSymbolAddress((void**)&csum, g_csum);

    // h1 = x1 @ W1^T + b1   (M=T, N=E, K=T)
    dim3 gh(E / BN, T / BM);
    gemm_nt<<<gh, 256>>>(x1, W1, b1, h1, T, E, T);
    // h2 = x2 @ W2^T + b2
    gemm_nt<<<gh, 256>>>(x2, W2, b2, h2, T, E, T);
    // dot = h1 @ h2^T       (M=T, N=T, K=E)
    dim3 gd(T / BN, T / BM);
    gemm_nt<<<gd, 256>>>(h1, h2, nullptr, dot, T, T, E);
    // lg = window(dot) + global_att
    dim3 gw(T / WC, T / WR);
    window_kernel<<<gw, 256>>>(dot, ga, lg);
    // column softmax stats
    colreduce<<<T / 32, 256>>>(lg, cmax, csum);
    // out = exp(lg - max)/sum
    finalize_kernel<<<((size_t)T * T / 4) / 256, 256>>>(lg, cmax, csum, out);
}

// round 4
// speedup vs baseline: 1.3377x; 1.3377x over previous
#include <cuda_runtime.h>
#include <cuda_bf16.h>
#include <cstdint>
#include <math.h>

// Problem dims (fixed by the dataset)
#define T 4096
#define E 512

// -------------------- scratch (allocation-free: __device__ globals) ---------
__device__ float g_h1[(size_t)T * E];
__device__ float g_h2[(size_t)T * E];
__device__ float g_dot[(size_t)T * T];
__device__ float g_lg[(size_t)T * T];
__device__ float g_cmax[T];
__device__ float g_csum[T];

// ==================== tf32-split GEMM via mma.sync ==========================
// C[m,n] = sum_k A[m,k]*B[n,k] (+bias[n])
// A: MxK row-major f32, B: NxK row-major f32, C: MxN row-major f32.
// Each f32 is split into hi=tf32(v), lo=tf32(v-hi); product = hi*hi+hi*lo+lo*hi.
#define BM 128
#define BN 128
#define BK 16
#define APAD 4                 // row stride 20 floats (80B, 16B aligned)
#define ASTR (BK + APAD)

__device__ __forceinline__ uint32_t smem_u32(const void* p) {
    uint32_t a;
    asm("{ .reg .u64 t; cvta.to.shared.u64 t, %1; cvt.u32.u64 %0, t; }"
        : "=r"(a) : "l"(p));
    return a;
}

__device__ __forceinline__ void cp_async16(uint32_t dst, const void* src) {
    asm volatile("cp.async.cg.shared.global [%0], [%1], 16;"
                 :: "r"(dst), "l"(src) : "memory");
}
#define CP_COMMIT() asm volatile("cp.async.commit_group;" ::: "memory")
#define CP_WAIT(N)  asm volatile("cp.async.wait_group %0;" :: "n"(N) : "memory")

__device__ __forceinline__ void tf32_split(float x, uint32_t& hb, uint32_t& lb) {
    asm("cvt.rna.tf32.f32 %0, %1;" : "=r"(hb) : "f"(x));
    float lf = x - __uint_as_float(hb);
    asm("cvt.rna.tf32.f32 %0, %1;" : "=r"(lb) : "f"(lf));
}

__device__ __forceinline__ void mma_16n8k8(float* c, const uint32_t* a,
                                           const uint32_t* b) {
    asm volatile(
        "mma.sync.aligned.m16n8k8.row.col.f32.tf32.tf32.f32 "
        "{%0,%1,%2,%3}, {%4,%5,%6,%7}, {%8,%9}, {%0,%1,%2,%3};"
        : "+f"(c[0]), "+f"(c[1]), "+f"(c[2]), "+f"(c[3])
        : "r"(a[0]), "r"(a[1]), "r"(a[2]), "r"(a[3]), "r"(b[0]), "r"(b[1]));
}

__global__ __launch_bounds__(256) void gemm_tf32(const float* __restrict__ A,
                                                 const float* __restrict__ B,
                                                 const float* __restrict__ bias,
                                                 float* __restrict__ C,
                                                 int M, int N, int K) {
    __shared__ float As[2][BM][ASTR];
    __shared__ float Bs[2][BN][ASTR];

    const int tid = threadIdx.x;
    const int wid = tid >> 5;
    const int lane = tid & 31;
    const int m0 = blockIdx.y * BM;
    const int n0 = blockIdx.x * BN;

    // warp tile: 64 (M) x 32 (N); warp grid 2 x 4
    const int wm = (wid >> 2) * 64;     // 0 or 64
    const int wn = (wid & 3) * 32;      // 0,32,64,96

    const int qr = lane >> 2;           // lane quad-row 0..7
    const int qc = lane & 3;            // lane quad-col 0..3

    float acc[4][4][4];
#pragma unroll
    for (int i = 0; i < 4; i++)
#pragma unroll
        for (int j = 0; j < 4; j++)
#pragma unroll
            for (int v = 0; v < 4; v++) acc[i][j][v] = 0.f;

    const float* Abase = A + (size_t)m0 * K;
    const float* Bbase = B + (size_t)n0 * K;

    // per-thread cp.async mapping: 2 rows-of-4-float4 per tile
    const int lrow = tid >> 2;          // 0..63
    const int lq = tid & 3;             // float4 within row

    const int NC = K / BK;

    // ---- prologue: load chunk 0 into stage 0 ------------------------------
    {
        const int k0 = 0;
#pragma unroll
        for (int h = 0; h < 2; h++) {
            int row = lrow + h * 64;
            cp_async16(smem_u32(&As[0][row][lq * 4]),
                       Abase + (size_t)row * K + k0 + lq * 4);
            cp_async16(smem_u32(&Bs[0][row][lq * 4]),
                       Bbase + (size_t)row * K + k0 + lq * 4);
        }
        CP_COMMIT();
    }

    for (int c = 0; c < NC; c++) {
        const int s = c & 1;
        if (c + 1 < NC) {
            const int k0 = (c + 1) * BK;
            const int sn = (c + 1) & 1;
#pragma unroll
            for (int h = 0; h < 2; h++) {
                int row = lrow + h * 64;
                cp_async16(smem_u32(&As[sn][row][lq * 4]),
                           Abase + (size_t)row * K + k0 + lq * 4);
                cp_async16(smem_u32(&Bs[sn][row][lq * 4]),
                           Bbase + (size_t)row * K + k0 + lq * 4);
            }
            CP_COMMIT();
            CP_WAIT(1);
        } else {
            CP_WAIT(0);
        }
        __syncthreads();

        // ---- compute chunk s ----------------------------------------------
#pragma unroll
        for (int ks = 0; ks < BK; ks += 8) {
            // A fragments: 4 m-tiles, hi/lo
            uint32_t ahi[4][4], alo[4][4];
#pragma unroll
            for (int mt = 0; mt < 4; mt++) {
                const int mr = wm + mt * 16;
                float r0 = As[s][mr + qr][ks + qc];
                float r1 = As[s][mr + qr + 8][ks + qc];
                float r2 = As[s][mr + qr][ks + qc + 4];
                float r3 = As[s][mr + qr + 8][ks + qc + 4];
                tf32_split(r0, ahi[mt][0], alo[mt][0]);
                tf32_split(r1, ahi[mt][1], alo[mt][1]);
                tf32_split(r2, ahi[mt][2], alo[mt][2]);
                tf32_split(r3, ahi[mt][3], alo[mt][3]);
            }
            // B fragments: 4 n-tiles, hi/lo
            uint32_t bhi[4][2], blo[4][2];
#pragma unroll
            for (int nt = 0; nt < 4; nt++) {
                const int nr = wn + nt * 8;
                float r0 = Bs[s][nr + qr][ks + qc];
                float r1 = Bs[s][nr + qr][ks + qc + 4];
                tf32_split(r0, bhi[nt][0], blo[nt][0]);
                tf32_split(r1, bhi[nt][1], blo[nt][1]);
            }
#pragma unroll
            for (int mt = 0; mt < 4; mt++)
#pragma unroll
                for (int nt = 0; nt < 4; nt++) {
                    mma_16n8k8(acc[mt][nt], ahi[mt], bhi[nt]);
                    mma_16n8k8(acc[mt][nt], ahi[mt], blo[nt]);
                    mma_16n8k8(acc[mt][nt], alo[mt], bhi[nt]);
                }
        }
        __syncthreads();
    }

    // ---- epilogue ----------------------------------------------------------
#pragma unroll
    for (int mt = 0; mt < 4; mt++) {
#pragma unroll
        for (int nt = 0; nt < 4; nt++) {
            const int mrow = m0 + wm + mt * 16 + qr;
            const int ncol = n0 + wn + nt * 8 + qc * 2;
            float bx = 0.f, by = 0.f;
            if (bias) { bx = bias[ncol]; by = bias[ncol + 1]; }
            float2 v0 = make_float2(acc[mt][nt][0] + bx, acc[mt][nt][1] + by);
            float2 v1 = make_float2(acc[mt][nt][2] + bx, acc[mt][nt][3] + by);
            *(float2*)(C + (size_t)mrow * N + ncol) = v0;
            *(float2*)(C + (size_t)(mrow + 8) * N + ncol) = v1;
        }
    }
}

// -------------------- banded window sum + global add ------------------------
#define WR 128
#define WC 32
#define HALO 63

__global__ __launch_bounds__(256) void window_kernel(const float* __restrict__ dot,
                                                     const float* __restrict__ gatt,
                                                     float* __restrict__ lg) {
    __shared__ float s[WR + 2 * HALO][WC];

    const int r0 = blockIdx.y * WR;
    const int c0 = blockIdx.x * WC;
    const int tid = threadIdx.x;
    const int col = tid & 31;

    for (int rr = tid >> 5; rr < WR + 2 * HALO; rr += 8) {
        int gr = r0 - HALO + rr;
        float v = 0.f;
        if (gr >= 0 && gr < T) v = dot[(size_t)gr * T + c0 + col];
        s[rr][col] = v;
    }
    __syncthreads();

    const int strip = tid >> 5;
    const int i0 = strip * 16;

    float w0 = 0.f, w1 = 0.f, w2 = 0.f, w3 = 0.f;
#pragma unroll 8
    for (int t = 0; t < 124; t += 4) {
        w0 += s[i0 + t + 0][col];
        w1 += s[i0 + t + 1][col];
        w2 += s[i0 + t + 2][col];
        w3 += s[i0 + t + 3][col];
    }
    w0 += s[i0 + 124][col];
    w1 += s[i0 + 125][col];
    w2 += s[i0 + 126][col];
    float w = (w0 + w1) + (w2 + w3);

#pragma unroll
    for (int t = 0; t < 16; t++) {
        int gi = r0 + i0 + t;
        float val = w + gatt[(size_t)gi * T + c0 + col];
        lg[(size_t)gi * T + c0 + col] = val;
        if (t < 15) w += s[i0 + t + 127][col] - s[i0 + t][col];
    }
}

// -------------------- per-column max + sum(exp) -----------------------------
__global__ __launch_bounds__(256) void colreduce(const float* __restrict__ lg,
                                                 float* __restrict__ cmax,
                                                 float* __restrict__ csum) {
    const int c0 = blockIdx.x * 32;
    const int col = threadIdx.x & 31;
    const int seg = threadIdx.x >> 5;
    const int rbeg = seg * 512;

    __shared__ float sm[8][32];
    __shared__ float ss[8][32];

    float m0 = -1e30f, m1 = -1e30f, m2 = -1e30f, m3 = -1e30f;
    for (int r = rbeg; r < rbeg + 512; r += 4) {
        m0 = fmaxf(m0, lg[(size_t)(r + 0) * T + c0 + col]);
        m1 = fmaxf(m1, lg[(size_t)(r + 1) * T + c0 + col]);
        m2 = fmaxf(m2, lg[(size_t)(r + 2) * T + c0 + col]);
        m3 = fmaxf(m3, lg[(size_t)(r + 3) * T + c0 + col]);
    }
    sm[seg][col] = fmaxf(fmaxf(m0, m1), fmaxf(m2, m3));
    __syncthreads();
    if (seg == 0) {
        float mm = sm[0][col];
#pragma unroll
        for (int i = 1; i < 8; i++) mm = fmaxf(mm, sm[i][col]);
        sm[0][col] = mm;
    }
    __syncthreads();
    const float M = sm[0][col];

    float s0 = 0.f, s1 = 0.f, s2 = 0.f, s3 = 0.f;
    for (int r = rbeg; r < rbeg + 512; r += 4) {
        s0 += expf(lg[(size_t)(r + 0) * T + c0 + col] - M);
        s1 += expf(lg[(size_t)(r + 1) * T + c0 + col] - M);
        s2 += expf(lg[(size_t)(r + 2) * T + c0 + col] - M);
        s3 += expf(lg[(size_t)(r + 3) * T + c0 + col] - M);
    }
    ss[seg][col] = (s0 + s1) + (s2 + s3);
    __syncthreads();
    if (seg == 0) {
        float tt = 0.f;
#pragma unroll
        for (int i = 0; i < 8; i++) tt += ss[i][col];
        cmax[c0 + col] = M;
        csum[c0 + col] = tt;
    }
}

// -------------------- finalize: out = exp(lg - max_col) / sum_col -----------
__global__ __launch_bounds__(256) void finalize_kernel(const float* __restrict__ lg,
                                                       const float* __restrict__ cmax,
                                                       const float* __restrict__ csum,
                                                       float* __restrict__ out) {
    size_t i = (size_t)blockIdx.x * blockDim.x + threadIdx.x;
    size_t base = i * 4;
    int c = (int)(base & (T - 1));
    float4 v = *(const float4*)(lg + base);
    float4 M = *(const float4*)(cmax + c);
    float4 S = *(const float4*)(csum + c);
    float4 o;
    o.x = expf(v.x - M.x) / S.x;
    o.y = expf(v.y - M.y) / S.y;
    o.z = expf(v.z - M.z) / S.z;
    o.w = expf(v.w - M.w) / S.w;
    *(float4*)(out + base) = o;
}

// -------------------- launch ------------------------------------------------
extern "C" void kernel_launch(void* const* d_in, const int* in_sizes, int n_in,
                              void* d_out, int out_size) {
    const float* x1 = (const float*)d_in[0];   // (T, T)
    const float* x2 = (const float*)d_in[1];   // (T, T)
    const float* W1 = (const float*)d_in[2];   // (E, T)
    const float* b1 = (const float*)d_in[3];   // (E,)
    const float* W2 = (const float*)d_in[4];   // (E, T)
    const float* b2 = (const float*)d_in[5];   // (E,)
    const float* ga = (const float*)d_in[6];   // (T, T)
    float* out = (float*)d_out;

    float *h1, *h2, *dot, *lg, *cmax, *csum;
    cudaGetSymbolAddress((void**)&h1, g_h1);
    cudaGetSymbolAddress((void**)&h2, g_h2);
    cudaGetSymbolAddress((void**)&dot, g_dot);
    cudaGetSymbolAddress((void**)&lg, g_lg);
    cudaGetSymbolAddress((void**)&cmax, g_cmax);
    cudaGetSymbolAddress((void**)&csum, g_csum);

    // h1 = x1 @ W1^T + b1   (M=T, N=E, K=T)
    gemm_tf32<<<dim3(E / BN, T / BM), 256>>>(x1, W1, b1, h1, T, E, T);
    // h2 = x2 @ W2^T + b2
    gemm_tf32<<<dim3(E / BN, T / BM), 256>>>(x2, W2, b2, h2, T, E, T);
    // dot = h1 @ h2^T       (M=T, N=T, K=E)
    gemm_tf32<<<dim3(T / BN, T / BM), 256>>>(h1, h2, nullptr, dot, T, T, E);
    // lg = window(dot) + global_att
    window_kernel<<<dim3(T / WC, T / WR), 256>>>(dot, ga, lg);
    // column softmax stats
    colreduce<<<T / 32, 256>>>(lg, cmax, csum);
    // out = exp(lg - max)/sum
    finalize_kernel<<<((size_t)T * T / 4) / 256, 256>>>(lg, cmax, csum, out);
}